// round 2
// baseline (speedup 1.0000x reference)
#include <cuda_runtime.h>

#define NB    8
#define NN    128
#define SS    100
#define F1    160
#define IMG   1024   // NB*NN

// ---------------- scratch (device globals; no allocations allowed) ----------
__device__ float g_Hf [IMG * F1];
__device__ float g_dkf[IMG * 512];
__device__ float g_xx [IMG];
__device__ float g_K  [IMG * NN];
__device__ float g_Ha [IMG * F1];
__device__ float g_Hb [IMG * F1];

// ---------------- fused conv stack: 4 x (conv3x3 VALID + relu + maxpool2) ---
// smem float offsets
#define SO_IN 0          // 100*100 = 10000
#define SO_P1 10000      // 10*49*49 = 24010
#define SO_P2 34010      // 10*23*23 = 5290
#define SO_P3 39300      // 10*10*10 = 1000
#define SO_W  40300      // up to 900
#define SO_B  41200      // 10
#define SMEM_FLOATS 41216
#define SMEM_BYTES (SMEM_FLOATS * 4)

__global__ void __launch_bounds__(256, 1)
conv_all(const float* __restrict__ H,
         const float* __restrict__ w1, const float* __restrict__ b1,
         const float* __restrict__ w2, const float* __restrict__ b2,
         const float* __restrict__ w3, const float* __restrict__ b3,
         const float* __restrict__ w4, const float* __restrict__ b4)
{
    extern __shared__ float sm[];
    float* s_in = sm + SO_IN;
    float* s_p1 = sm + SO_P1;
    float* s_p2 = sm + SO_P2;
    float* s_p3 = sm + SO_P3;
    float* s_w  = sm + SO_W;
    float* s_b  = sm + SO_B;

    const int tid = threadIdx.x;
    const int img = blockIdx.x;

    // ---- load image + w1 ----
    {
        const float* src = H + (size_t)img * (SS * SS);
        for (int i = tid; i < SS * SS; i += 256) s_in[i] = src[i];
        for (int i = tid; i < 90; i += 256) s_w[i] = w1[i];
        if (tid < 10) s_b[tid] = b1[tid];
    }
    __syncthreads();

    // ---- stage 1: conv1 (1->10), out pooled 10x49x49 ----
    #pragma unroll 1
    for (int cell = tid; cell < 49 * 49; cell += 256) {
        const int py = cell / 49, px = cell % 49;
        float in[4][4];
        #pragma unroll
        for (int dy = 0; dy < 4; dy++)
            #pragma unroll
            for (int dx = 0; dx < 4; dx++)
                in[dy][dx] = s_in[(2 * py + dy) * SS + 2 * px + dx];
        #pragma unroll
        for (int oc = 0; oc < 10; oc++) {
            float bb = s_b[oc];
            float a0 = bb, a1 = bb, a2 = bb, a3 = bb;
            #pragma unroll
            for (int ky = 0; ky < 3; ky++)
                #pragma unroll
                for (int kx = 0; kx < 3; kx++) {
                    const float w = s_w[oc * 9 + ky * 3 + kx];
                    a0 = fmaf(w, in[ky][kx],         a0);
                    a1 = fmaf(w, in[ky][kx + 1],     a1);
                    a2 = fmaf(w, in[ky + 1][kx],     a2);
                    a3 = fmaf(w, in[ky + 1][kx + 1], a3);
                }
            const float m = fmaxf(fmaxf(a0, a1), fmaxf(a2, a3));
            s_p1[(oc * 49 + py) * 49 + px] = fmaxf(m, 0.f);
        }
    }
    __syncthreads();
    for (int i = tid; i < 900; i += 256) s_w[i] = w2[i];
    if (tid < 10) s_b[tid] = b2[tid];
    __syncthreads();

    // ---- stage 2: conv2 (10->10), in 10x49x49 -> pooled 10x23x23 ----
    #pragma unroll 1
    for (int cell = tid; cell < 23 * 23; cell += 256) {
        const int py = cell / 23, px = cell % 23;
        float acc[10][4];
        #pragma unroll
        for (int oc = 0; oc < 10; oc++) {
            const float bb = s_b[oc];
            acc[oc][0] = bb; acc[oc][1] = bb; acc[oc][2] = bb; acc[oc][3] = bb;
        }
        #pragma unroll 1
        for (int ic = 0; ic < 10; ic++) {
            float in[4][4];
            #pragma unroll
            for (int dy = 0; dy < 4; dy++)
                #pragma unroll
                for (int dx = 0; dx < 4; dx++)
                    in[dy][dx] = s_p1[(ic * 49 + 2 * py + dy) * 49 + 2 * px + dx];
            #pragma unroll
            for (int oc = 0; oc < 10; oc++)
                #pragma unroll
                for (int ky = 0; ky < 3; ky++)
                    #pragma unroll
                    for (int kx = 0; kx < 3; kx++) {
                        const float w = s_w[((oc * 10 + ic) * 3 + ky) * 3 + kx];
                        acc[oc][0] = fmaf(w, in[ky][kx],         acc[oc][0]);
                        acc[oc][1] = fmaf(w, in[ky][kx + 1],     acc[oc][1]);
                        acc[oc][2] = fmaf(w, in[ky + 1][kx],     acc[oc][2]);
                        acc[oc][3] = fmaf(w, in[ky + 1][kx + 1], acc[oc][3]);
                    }
        }
        #pragma unroll
        for (int oc = 0; oc < 10; oc++) {
            const float m = fmaxf(fmaxf(acc[oc][0], acc[oc][1]),
                                  fmaxf(acc[oc][2], acc[oc][3]));
            s_p2[(oc * 23 + py) * 23 + px] = fmaxf(m, 0.f);
        }
    }
    __syncthreads();
    for (int i = tid; i < 900; i += 256) s_w[i] = w3[i];
    if (tid < 10) s_b[tid] = b3[tid];
    __syncthreads();

    // ---- stage 3: conv3 (10->10), in 10x23x23 -> pooled 10x10x10 ----
    #pragma unroll 1
    for (int cell = tid; cell < 10 * 10; cell += 256) {
        const int py = cell / 10, px = cell % 10;
        float acc[10][4];
        #pragma unroll
        for (int oc = 0; oc < 10; oc++) {
            const float bb = s_b[oc];
            acc[oc][0] = bb; acc[oc][1] = bb; acc[oc][2] = bb; acc[oc][3] = bb;
        }
        #pragma unroll 1
        for (int ic = 0; ic < 10; ic++) {
            float in[4][4];
            #pragma unroll
            for (int dy = 0; dy < 4; dy++)
                #pragma unroll
                for (int dx = 0; dx < 4; dx++)
                    in[dy][dx] = s_p2[(ic * 23 + 2 * py + dy) * 23 + 2 * px + dx];
            #pragma unroll
            for (int oc = 0; oc < 10; oc++)
                #pragma unroll
                for (int ky = 0; ky < 3; ky++)
                    #pragma unroll
                    for (int kx = 0; kx < 3; kx++) {
                        const float w = s_w[((oc * 10 + ic) * 3 + ky) * 3 + kx];
                        acc[oc][0] = fmaf(w, in[ky][kx],         acc[oc][0]);
                        acc[oc][1] = fmaf(w, in[ky][kx + 1],     acc[oc][1]);
                        acc[oc][2] = fmaf(w, in[ky + 1][kx],     acc[oc][2]);
                        acc[oc][3] = fmaf(w, in[ky + 1][kx + 1], acc[oc][3]);
                    }
        }
        #pragma unroll
        for (int oc = 0; oc < 10; oc++) {
            const float m = fmaxf(fmaxf(acc[oc][0], acc[oc][1]),
                                  fmaxf(acc[oc][2], acc[oc][3]));
            s_p3[(oc * 10 + py) * 10 + px] = fmaxf(m, 0.f);
        }
    }
    __syncthreads();
    for (int i = tid; i < 900; i += 256) s_w[i] = w4[i];
    if (tid < 10) s_b[tid] = b4[tid];
    __syncthreads();

    // ---- stage 4: conv4 (10->10), in 10x10x10 -> pooled 10x4x4 = Hf[160] ----
    if (tid < 16) {
        const int py = tid / 4, px = tid % 4;
        float acc[10][4];
        #pragma unroll
        for (int oc = 0; oc < 10; oc++) {
            const float bb = s_b[oc];
            acc[oc][0] = bb; acc[oc][1] = bb; acc[oc][2] = bb; acc[oc][3] = bb;
        }
        #pragma unroll 1
        for (int ic = 0; ic < 10; ic++) {
            float in[4][4];
            #pragma unroll
            for (int dy = 0; dy < 4; dy++)
                #pragma unroll
                for (int dx = 0; dx < 4; dx++)
                    in[dy][dx] = s_p3[(ic * 10 + 2 * py + dy) * 10 + 2 * px + dx];
            #pragma unroll
            for (int oc = 0; oc < 10; oc++)
                #pragma unroll
                for (int ky = 0; ky < 3; ky++)
                    #pragma unroll
                    for (int kx = 0; kx < 3; kx++) {
                        const float w = s_w[((oc * 10 + ic) * 3 + ky) * 3 + kx];
                        acc[oc][0] = fmaf(w, in[ky][kx],         acc[oc][0]);
                        acc[oc][1] = fmaf(w, in[ky][kx + 1],     acc[oc][1]);
                        acc[oc][2] = fmaf(w, in[ky + 1][kx],     acc[oc][2]);
                        acc[oc][3] = fmaf(w, in[ky + 1][kx + 1], acc[oc][3]);
                    }
        }
        #pragma unroll
        for (int oc = 0; oc < 10; oc++) {
            const float m = fmaxf(fmaxf(acc[oc][0], acc[oc][1]),
                                  fmaxf(acc[oc][2], acc[oc][3]));
            g_Hf[(size_t)img * F1 + oc * 16 + py * 4 + px] = fmaxf(m, 0.f);
        }
    }
}

// ---------------- deep-kernel MLP: 160 -> tanh 256 -> tanh 512 (+ ||x||^2) --
__global__ void __launch_bounds__(256)
dk_kernel(const float* __restrict__ Wdk1, const float* __restrict__ bdk1,
          const float* __restrict__ Wdk2, const float* __restrict__ bdk2)
{
    __shared__ __align__(16) float hf[F1];
    __shared__ __align__(16) float t1[256];
    __shared__ float red[8];
    const int tid = threadIdx.x, img = blockIdx.x;

    const float* hrow = g_Hf + (size_t)img * F1;
    if (tid < F1) hf[tid] = hrow[tid];
    __syncthreads();

    {
        float acc = bdk1[tid];
        const float4* w  = (const float4*)(Wdk1 + (size_t)tid * F1);
        const float4* h4 = (const float4*)hf;
        #pragma unroll 8
        for (int j = 0; j < 40; j++) {
            const float4 a = h4[j], b = w[j];
            acc += a.x * b.x + a.y * b.y + a.z * b.z + a.w * b.w;
        }
        t1[tid] = tanhf(acc);
    }
    __syncthreads();

    float sq = 0.f;
    #pragma unroll
    for (int r = 0; r < 2; r++) {
        const int o = tid + r * 256;
        float acc = bdk2[o];
        const float4* w  = (const float4*)(Wdk2 + (size_t)o * 256);
        const float4* t4 = (const float4*)t1;
        #pragma unroll 8
        for (int j = 0; j < 64; j++) {
            const float4 a = t4[j], b = w[j];
            acc += a.x * b.x + a.y * b.y + a.z * b.z + a.w * b.w;
        }
        const float v = tanhf(acc);
        g_dkf[(size_t)img * 512 + o] = v;
        sq += v * v;
    }
    #pragma unroll
    for (int o = 16; o > 0; o >>= 1) sq += __shfl_xor_sync(0xffffffffu, sq, o);
    if ((tid & 31) == 0) red[tid >> 5] = sq;
    __syncthreads();
    if (tid == 0) {
        float s = 0.f;
        #pragma unroll
        for (int i = 0; i < 8; i++) s += red[i];
        g_xx[img] = s;
    }
}

// ---------------- Gram matrix + softmax (mean-centering is softmax-invariant)
__global__ void __launch_bounds__(128)
gram_kernel(const float* __restrict__ sigma)
{
    __shared__ __align__(16) float xn[512];
    __shared__ float red[4];
    const int tid = threadIdx.x, bn = blockIdx.x, b = bn >> 7;

    const float* xr = g_dkf + (size_t)bn * 512;
    for (int i = tid; i < 512; i += 128) xn[i] = xr[i];
    __syncthreads();

    const float4* xm = (const float4*)(g_dkf + (size_t)(b * NN + tid) * 512);
    const float4* x4 = (const float4*)xn;
    float dot = 0.f;
    #pragma unroll 8
    for (int j = 0; j < 128; j++) {
        const float4 a = x4[j], c = xm[j];
        dot += a.x * c.x + a.y * c.y + a.z * c.z + a.w * c.w;
    }
    const float k = -(g_xx[bn] + g_xx[b * NN + tid] - 2.f * dot) / sigma[0];

    float mx = k;
    #pragma unroll
    for (int o = 16; o > 0; o >>= 1) mx = fmaxf(mx, __shfl_xor_sync(0xffffffffu, mx, o));
    if ((tid & 31) == 0) red[tid >> 5] = mx;
    __syncthreads();
    mx = fmaxf(fmaxf(red[0], red[1]), fmaxf(red[2], red[3]));
    const float e = expf(k - mx);
    __syncthreads();

    float s = e;
    #pragma unroll
    for (int o = 16; o > 0; o >>= 1) s += __shfl_xor_sync(0xffffffffu, s, o);
    if ((tid & 31) == 0) red[tid >> 5] = s;
    __syncthreads();
    s = red[0] + red[1] + red[2] + red[3];

    g_K[(size_t)bn * NN + tid] = e / s;
}

// ---------------- one message-passing + transform round ---------------------
__global__ void __launch_bounds__(160)
round_kernel(int zsel, const float* __restrict__ Wt, const float* __restrict__ bt,
             int osel)
{
    __shared__ float krow[NN];
    __shared__ __align__(16) float u[F1];
    const int tid = threadIdx.x, bn = blockIdx.x, b = bn >> 7;

    const float* Z = (zsel == 0) ? g_Hf : ((zsel == 1) ? g_Ha : g_Hb);
    float* Hout = (osel == 1) ? g_Ha : g_Hb;

    if (tid < NN) krow[tid] = g_K[(size_t)bn * NN + tid];
    __syncthreads();

    const float* zb = Z + (size_t)(b * NN) * F1 + tid;
    float h = 0.f;
    #pragma unroll 8
    for (int m = 0; m < NN; m++) h = fmaf(krow[m], zb[(size_t)m * F1], h);

    u[tid] = 0.5f * (Z[(size_t)bn * F1 + tid] + h);
    __syncthreads();

    float acc = bt[tid];
    const float4* w4 = (const float4*)(Wt + (size_t)tid * F1);
    const float4* u4 = (const float4*)u;
    #pragma unroll 8
    for (int j = 0; j < 40; j++) {
        const float4 a = u4[j], bw = w4[j];
        acc += a.x * bw.x + a.y * bw.y + a.z * bw.z + a.w * bw.w;
    }
    Hout[(size_t)bn * F1 + tid] = tanhf(acc);
}

// ---------------- final: max over N, linear head, exp ------------------------
__global__ void __launch_bounds__(160)
final_kernel(const float* __restrict__ Wc, const float* __restrict__ bc,
             float* __restrict__ out)
{
    __shared__ float red[5];
    const int tid = threadIdx.x, b = blockIdx.x;

    const float* base = g_Ha + (size_t)(b * NN) * F1 + tid;   // H6 lives in g_Ha
    float m = -3.4e38f;
    #pragma unroll 8
    for (int n = 0; n < NN; n++) m = fmaxf(m, base[(size_t)n * F1]);

    float v = m * Wc[tid];
    #pragma unroll
    for (int o = 16; o > 0; o >>= 1) v += __shfl_xor_sync(0xffffffffu, v, o);
    if ((tid & 31) == 0) red[tid >> 5] = v;
    __syncthreads();
    if (tid == 0) {
        float s = 0.f;
        #pragma unroll
        for (int i = 0; i < 5; i++) s += red[i];
        out[b] = expf(s + bc[0]);
    }
}

// ---------------- launch -----------------------------------------------------
extern "C" void kernel_launch(void* const* d_in, const int* in_sizes, int n_in,
                              void* d_out, int out_size)
{
    const float* H    = (const float*)d_in[0];
    const float* w1   = (const float*)d_in[1];
    const float* b1   = (const float*)d_in[2];
    const float* w2   = (const float*)d_in[3];
    const float* b2   = (const float*)d_in[4];
    const float* w3   = (const float*)d_in[5];
    const float* b3   = (const float*)d_in[6];
    const float* w4   = (const float*)d_in[7];
    const float* b4   = (const float*)d_in[8];
    const float* Wdk1 = (const float*)d_in[9];
    const float* bdk1 = (const float*)d_in[10];
    const float* Wdk2 = (const float*)d_in[11];
    const float* bdk2 = (const float*)d_in[12];
    const float* Wt1  = (const float*)d_in[13];
    const float* bt1  = (const float*)d_in[14];
    const float* Wt2  = (const float*)d_in[15];
    const float* bt2  = (const float*)d_in[16];
    const float* Wt3  = (const float*)d_in[17];
    const float* bt3  = (const float*)d_in[18];
    const float* sigw = (const float*)d_in[19];
    const float* Wc   = (const float*)d_in[20];
    const float* bc   = (const float*)d_in[21];
    float* out = (float*)d_out;

    cudaFuncSetAttribute(conv_all, cudaFuncAttributeMaxDynamicSharedMemorySize,
                         SMEM_BYTES);

    conv_all<<<IMG, 256, SMEM_BYTES>>>(H, w1, b1, w2, b2, w3, b3, w4, b4);
    dk_kernel<<<IMG, 256>>>(Wdk1, bdk1, Wdk2, bdk2);
    gram_kernel<<<IMG, 128>>>(sigw);
    round_kernel<<<IMG, 160>>>(0, Wt1, bt1, 1);   // Z=Hf  -> H2 in g_Ha
    round_kernel<<<IMG, 160>>>(1, Wt2, bt2, 2);   // Z=H2  -> H4 in g_Hb
    round_kernel<<<IMG, 160>>>(2, Wt3, bt3, 1);   // Z=H4  -> H6 in g_Ha
    final_kernel<<<NB, 160>>>(Wc, bc, out);
}

// round 14
// speedup vs baseline: 1.6928x; 1.6928x over previous
#include <cuda_runtime.h>

#define NB    8
#define NN    128
#define SS    100
#define F1    160
#define IMG   1024   // NB*NN
#define CT    512    // conv_all threads

// ---------------- scratch (device globals; no allocations allowed) ----------
__device__ float g_Hf [IMG * F1];
__device__ float g_dkf[IMG * 512];
__device__ float g_xx [IMG];
__device__ float g_K  [IMG * NN];
__device__ float g_Ha [IMG * F1];
__device__ float g_Hb [IMG * F1];

// ---------------- fused conv stack: 4 x (conv3x3 VALID + relu + maxpool2) ---
#define SO_IN 0          // 100*100 = 10000
#define SO_P1 10000      // 10*49*49 = 24010
#define SO_P2 34010      // 10*23*23 = 5290
#define SO_P3 39300      // 10*10*10 = 1000
#define SO_W  40300      // up to 900
#define SO_B  41200      // 10
#define SMEM_FLOATS 41216
#define SMEM_BYTES (SMEM_FLOATS * 4)

__global__ void __launch_bounds__(CT, 1)
conv_all(const float* __restrict__ H,
         const float* __restrict__ w1, const float* __restrict__ b1,
         const float* __restrict__ w2, const float* __restrict__ b2,
         const float* __restrict__ w3, const float* __restrict__ b3,
         const float* __restrict__ w4, const float* __restrict__ b4)
{
    extern __shared__ float sm[];
    float* s_in = sm + SO_IN;
    float* s_p1 = sm + SO_P1;
    float* s_p2 = sm + SO_P2;
    float* s_p3 = sm + SO_P3;
    float* s_w  = sm + SO_W;
    float* s_b  = sm + SO_B;

    const int tid = threadIdx.x;
    const int img = blockIdx.x;

    // ---- load image + w1 ----
    {
        const float* src = H + (size_t)img * (SS * SS);
        for (int i = tid; i < SS * SS; i += CT) s_in[i] = src[i];
        for (int i = tid; i < 90; i += CT) s_w[i] = w1[i];
        if (tid < 10) s_b[tid] = b1[tid];
    }
    __syncthreads();

    // ---- stage 1: conv1 (1->10), out pooled 10x49x49 ----
    #pragma unroll 1
    for (int cell = tid; cell < 49 * 49; cell += CT) {
        const int py = cell / 49, px = cell % 49;
        float in[4][4];
        #pragma unroll
        for (int dy = 0; dy < 4; dy++)
            #pragma unroll
            for (int dx = 0; dx < 4; dx++)
                in[dy][dx] = s_in[(2 * py + dy) * SS + 2 * px + dx];
        #pragma unroll
        for (int oc = 0; oc < 10; oc++) {
            float bb = s_b[oc];
            float a0 = bb, a1 = bb, a2 = bb, a3 = bb;
            #pragma unroll
            for (int ky = 0; ky < 3; ky++)
                #pragma unroll
                for (int kx = 0; kx < 3; kx++) {
                    const float w = s_w[oc * 9 + ky * 3 + kx];
                    a0 = fmaf(w, in[ky][kx],         a0);
                    a1 = fmaf(w, in[ky][kx + 1],     a1);
                    a2 = fmaf(w, in[ky + 1][kx],     a2);
                    a3 = fmaf(w, in[ky + 1][kx + 1], a3);
                }
            const float m = fmaxf(fmaxf(a0, a1), fmaxf(a2, a3));
            s_p1[(oc * 49 + py) * 49 + px] = fmaxf(m, 0.f);
        }
    }
    __syncthreads();
    for (int i = tid; i < 900; i += CT) s_w[i] = w2[i];
    if (tid < 10) s_b[tid] = b2[tid];
    __syncthreads();

    // ---- stage 2: conv2 (10->10), 10x49x49 -> pooled 10x23x23 ----
    #pragma unroll 1
    for (int cell = tid; cell < 23 * 23; cell += CT) {
        const int py = cell / 23, px = cell % 23;
        float acc[10][4];
        #pragma unroll
        for (int oc = 0; oc < 10; oc++) {
            const float bb = s_b[oc];
            acc[oc][0] = bb; acc[oc][1] = bb; acc[oc][2] = bb; acc[oc][3] = bb;
        }
        #pragma unroll 1
        for (int ic = 0; ic < 10; ic++) {
            float in[4][4];
            #pragma unroll
            for (int dy = 0; dy < 4; dy++)
                #pragma unroll
                for (int dx = 0; dx < 4; dx++)
                    in[dy][dx] = s_p1[(ic * 49 + 2 * py + dy) * 49 + 2 * px + dx];
            #pragma unroll
            for (int oc = 0; oc < 10; oc++)
                #pragma unroll
                for (int ky = 0; ky < 3; ky++)
                    #pragma unroll
                    for (int kx = 0; kx < 3; kx++) {
                        const float w = s_w[((oc * 10 + ic) * 3 + ky) * 3 + kx];
                        acc[oc][0] = fmaf(w, in[ky][kx],         acc[oc][0]);
                        acc[oc][1] = fmaf(w, in[ky][kx + 1],     acc[oc][1]);
                        acc[oc][2] = fmaf(w, in[ky + 1][kx],     acc[oc][2]);
                        acc[oc][3] = fmaf(w, in[ky + 1][kx + 1], acc[oc][3]);
                    }
        }
        #pragma unroll
        for (int oc = 0; oc < 10; oc++) {
            const float m = fmaxf(fmaxf(acc[oc][0], acc[oc][1]),
                                  fmaxf(acc[oc][2], acc[oc][3]));
            s_p2[(oc * 23 + py) * 23 + px] = fmaxf(m, 0.f);
        }
    }
    __syncthreads();
    for (int i = tid; i < 900; i += CT) s_w[i] = w3[i];
    if (tid < 10) s_b[tid] = b3[tid];
    __syncthreads();

    // ---- stage 3: conv3 (10->10), 10x23x23 -> pooled 10x10x10 ----
    // 5 groups x 2 oc x 100 cells => 500 active threads
    if (tid < 500) {
        const int cell = tid % 100;
        const int g    = tid / 100;          // 0..4
        const int py = cell / 10, px = cell % 10;
        float acc[2][4];
        #pragma unroll
        for (int o = 0; o < 2; o++) {
            const float bb = s_b[g * 2 + o];
            acc[o][0] = bb; acc[o][1] = bb; acc[o][2] = bb; acc[o][3] = bb;
        }
        #pragma unroll 1
        for (int ic = 0; ic < 10; ic++) {
            float in[4][4];
            #pragma unroll
            for (int dy = 0; dy < 4; dy++)
                #pragma unroll
                for (int dx = 0; dx < 4; dx++)
                    in[dy][dx] = s_p2[(ic * 23 + 2 * py + dy) * 23 + 2 * px + dx];
            #pragma unroll
            for (int o = 0; o < 2; o++) {
                const int oc = g * 2 + o;
                #pragma unroll
                for (int ky = 0; ky < 3; ky++)
                    #pragma unroll
                    for (int kx = 0; kx < 3; kx++) {
                        const float w = s_w[((oc * 10 + ic) * 3 + ky) * 3 + kx];
                        acc[o][0] = fmaf(w, in[ky][kx],         acc[o][0]);
                        acc[o][1] = fmaf(w, in[ky][kx + 1],     acc[o][1]);
                        acc[o][2] = fmaf(w, in[ky + 1][kx],     acc[o][2]);
                        acc[o][3] = fmaf(w, in[ky + 1][kx + 1], acc[o][3]);
                    }
            }
        }
        #pragma unroll
        for (int o = 0; o < 2; o++) {
            const float m = fmaxf(fmaxf(acc[o][0], acc[o][1]),
                                  fmaxf(acc[o][2], acc[o][3]));
            s_p3[((g * 2 + o) * 10 + py) * 10 + px] = fmaxf(m, 0.f);
        }
    }
    __syncthreads();
    for (int i = tid; i < 900; i += CT) s_w[i] = w4[i];
    if (tid < 10) s_b[tid] = b4[tid];
    __syncthreads();

    // ---- stage 4: conv4 (10->10), 10x10x10 -> pooled 10x4x4 = Hf[160] ----
    if (tid < 160) {
        const int cell = tid & 15;
        const int oc   = tid >> 4;
        const int py = cell / 4, px = cell % 4;
        const float bb = s_b[oc];
        float a0 = bb, a1 = bb, a2 = bb, a3 = bb;
        #pragma unroll 1
        for (int ic = 0; ic < 10; ic++) {
            float in[4][4];
            #pragma unroll
            for (int dy = 0; dy < 4; dy++)
                #pragma unroll
                for (int dx = 0; dx < 4; dx++)
                    in[dy][dx] = s_p3[(ic * 10 + 2 * py + dy) * 10 + 2 * px + dx];
            #pragma unroll
            for (int ky = 0; ky < 3; ky++)
                #pragma unroll
                for (int kx = 0; kx < 3; kx++) {
                    const float w = s_w[((oc * 10 + ic) * 3 + ky) * 3 + kx];
                    a0 = fmaf(w, in[ky][kx],         a0);
                    a1 = fmaf(w, in[ky][kx + 1],     a1);
                    a2 = fmaf(w, in[ky + 1][kx],     a2);
                    a3 = fmaf(w, in[ky + 1][kx + 1], a3);
                }
        }
        const float m = fmaxf(fmaxf(a0, a1), fmaxf(a2, a3));
        g_Hf[(size_t)img * F1 + oc * 16 + py * 4 + px] = fmaxf(m, 0.f);
    }
}

// ---------------- deep-kernel MLP, 8 images per block ------------------------
// 160 -> tanh 256 -> tanh 512, plus ||dkf||^2
__global__ void __launch_bounds__(256)
dk_kernel(const float* __restrict__ Wdk1, const float* __restrict__ bdk1,
          const float* __restrict__ Wdk2, const float* __restrict__ bdk2)
{
    __shared__ __align__(16) float s_hf[8 * F1];    // 8 x 160
    __shared__ __align__(16) float s_t1[8 * 256];   // 8 x 256
    __shared__ float s_red[8 * 8];
    const int tid  = threadIdx.x;
    const int img0 = blockIdx.x * 8;

    for (int idx = tid; idx < 8 * F1; idx += 256) {
        const int i = idx / F1, f = idx % F1;
        s_hf[i * F1 + f] = g_Hf[(size_t)(img0 + i) * F1 + f];
    }
    __syncthreads();

    // layer 1: each thread computes output `tid` for all 8 images
    {
        const float b0 = bdk1[tid];
        float acc[8];
        #pragma unroll
        for (int i = 0; i < 8; i++) acc[i] = b0;
        const float4* w = (const float4*)(Wdk1 + (size_t)tid * F1);
        #pragma unroll 4
        for (int j = 0; j < 40; j++) {
            const float4 ww = w[j];
            #pragma unroll
            for (int i = 0; i < 8; i++) {
                const float4 h = ((const float4*)s_hf)[i * 40 + j];
                acc[i] += h.x * ww.x + h.y * ww.y + h.z * ww.z + h.w * ww.w;
            }
        }
        #pragma unroll
        for (int i = 0; i < 8; i++) s_t1[i * 256 + tid] = tanhf(acc[i]);
    }
    __syncthreads();

    // layer 2: two output halves, each thread does output tid and tid+256
    float sq[8];
    #pragma unroll
    for (int i = 0; i < 8; i++) sq[i] = 0.f;
    #pragma unroll 1
    for (int half = 0; half < 2; half++) {
        const int o = tid + half * 256;
        const float b0 = bdk2[o];
        float acc[8];
        #pragma unroll
        for (int i = 0; i < 8; i++) acc[i] = b0;
        const float4* w = (const float4*)(Wdk2 + (size_t)o * 256);
        #pragma unroll 4
        for (int j = 0; j < 64; j++) {
            const float4 ww = w[j];
            #pragma unroll
            for (int i = 0; i < 8; i++) {
                const float4 t = ((const float4*)s_t1)[i * 64 + j];
                acc[i] += t.x * ww.x + t.y * ww.y + t.z * ww.z + t.w * ww.w;
            }
        }
        #pragma unroll
        for (int i = 0; i < 8; i++) {
            const float v = tanhf(acc[i]);
            g_dkf[(size_t)(img0 + i) * 512 + o] = v;
            sq[i] += v * v;
        }
    }
    // reduce sq over threads for each image
    #pragma unroll
    for (int off = 16; off > 0; off >>= 1)
        #pragma unroll
        for (int i = 0; i < 8; i++)
            sq[i] += __shfl_xor_sync(0xffffffffu, sq[i], off);
    if ((tid & 31) == 0) {
        const int w = tid >> 5;
        #pragma unroll
        for (int i = 0; i < 8; i++) s_red[w * 8 + i] = sq[i];
    }
    __syncthreads();
    if (tid < 8) {
        float s = 0.f;
        #pragma unroll
        for (int w = 0; w < 8; w++) s += s_red[w * 8 + tid];
        g_xx[img0 + tid] = s;
    }
}

// ---------------- Gram + softmax, 4 rows per block ---------------------------
// (mean-centering before softmax is a per-row constant: dropped)
__global__ void __launch_bounds__(128)
gram_kernel(const float* __restrict__ sigma)
{
    __shared__ __align__(16) float s_xn[4 * 512];
    __shared__ float s_red[4][4];
    const int tid  = threadIdx.x;          // = m
    const int b    = blockIdx.x >> 5;
    const int tile = blockIdx.x & 31;
    const int n0   = tile * 4;

    for (int idx = tid; idx < 4 * 512; idx += 128) {
        const int r = idx >> 9, c = idx & 511;
        s_xn[idx] = g_dkf[(size_t)(b * NN + n0 + r) * 512 + c];
    }
    __syncthreads();

    const float inv_sig = 1.f / sigma[0];
    const float xxm = g_xx[b * NN + tid];
    float xxr[4];
    #pragma unroll
    for (int r = 0; r < 4; r++) xxr[r] = g_xx[b * NN + n0 + r];

    const float4* xm = (const float4*)(g_dkf + (size_t)(b * NN + tid) * 512);
    float dot[4] = {0.f, 0.f, 0.f, 0.f};
    #pragma unroll 4
    for (int j = 0; j < 128; j++) {
        const float4 c = xm[j];
        #pragma unroll
        for (int r = 0; r < 4; r++) {
            const float4 a = ((const float4*)s_xn)[r * 128 + j];
            dot[r] += a.x * c.x + a.y * c.y + a.z * c.z + a.w * c.w;
        }
    }
    float k[4];
    #pragma unroll
    for (int r = 0; r < 4; r++)
        k[r] = -(xxr[r] + xxm - 2.f * dot[r]) * inv_sig;

    // row max over the 128 threads (m-dim), 4 rows at once
    float mx[4];
    #pragma unroll
    for (int r = 0; r < 4; r++) mx[r] = k[r];
    #pragma unroll
    for (int off = 16; off > 0; off >>= 1)
        #pragma unroll
        for (int r = 0; r < 4; r++)
            mx[r] = fmaxf(mx[r], __shfl_xor_sync(0xffffffffu, mx[r], off));
    if ((tid & 31) == 0) {
        const int w = tid >> 5;
        #pragma unroll
        for (int r = 0; r < 4; r++) s_red[w][r] = mx[r];
    }
    __syncthreads();
    #pragma unroll
    for (int r = 0; r < 4; r++)
        mx[r] = fmaxf(fmaxf(s_red[0][r], s_red[1][r]),
                      fmaxf(s_red[2][r], s_red[3][r]));
    __syncthreads();

    float e[4], s[4];
    #pragma unroll
    for (int r = 0; r < 4; r++) { e[r] = expf(k[r] - mx[r]); s[r] = e[r]; }
    #pragma unroll
    for (int off = 16; off > 0; off >>= 1)
        #pragma unroll
        for (int r = 0; r < 4; r++)
            s[r] += __shfl_xor_sync(0xffffffffu, s[r], off);
    if ((tid & 31) == 0) {
        const int w = tid >> 5;
        #pragma unroll
        for (int r = 0; r < 4; r++) s_red[w][r] = s[r];
    }
    __syncthreads();
    #pragma unroll
    for (int r = 0; r < 4; r++) {
        const float sum = s_red[0][r] + s_red[1][r] + s_red[2][r] + s_red[3][r];
        g_K[(size_t)(b * NN + n0 + r) * NN + tid] = e[r] / sum;
    }
}

// ---------------- one message-passing + transform round, 4 rows per block ---
__global__ void __launch_bounds__(160)
round_kernel(int zsel, const float* __restrict__ Wt, const float* __restrict__ bt,
             int osel)
{
    __shared__ float s_k[4 * NN];                 // 4 x 128
    __shared__ __align__(16) float s_u[4 * F1];   // 4 x 160
    const int tid  = threadIdx.x;                 // feature index
    const int b    = blockIdx.x >> 5;
    const int tile = blockIdx.x & 31;
    const int n0   = tile * 4;

    const float* Z = (zsel == 0) ? g_Hf : ((zsel == 1) ? g_Ha : g_Hb);
    float* Hout = (osel == 1) ? g_Ha : g_Hb;

    for (int idx = tid; idx < 4 * NN; idx += 160) {
        const int r = idx >> 7, m = idx & 127;
        s_k[idx] = g_K[(size_t)(b * NN + n0 + r) * NN + m];
    }
    __syncthreads();

    // h[r] = sum_m K[n0+r, m] * Z[b, m, tid]
    float acc[4] = {0.f, 0.f, 0.f, 0.f};
    const float* zb = Z + (size_t)(b * NN) * F1 + tid;
    #pragma unroll 4
    for (int m = 0; m < NN; m++) {
        const float z = zb[(size_t)m * F1];
        #pragma unroll
        for (int r = 0; r < 4; r++)
            acc[r] = fmaf(s_k[r * NN + m], z, acc[r]);
    }
    #pragma unroll
    for (int r = 0; r < 4; r++)
        s_u[r * F1 + tid] = 0.5f * (Z[(size_t)(b * NN + n0 + r) * F1 + tid] + acc[r]);
    __syncthreads();

    // out[r, tid] = tanh( Wt[tid,:] . u[r,:] + bt[tid] )
    const float bb = bt[tid];
    float a2[4] = {bb, bb, bb, bb};
    const float4* w4 = (const float4*)(Wt + (size_t)tid * F1);
    #pragma unroll 4
    for (int j = 0; j < 40; j++) {
        const float4 ww = w4[j];
        #pragma unroll
        for (int r = 0; r < 4; r++) {
            const float4 u = ((const float4*)s_u)[r * 40 + j];
            a2[r] += u.x * ww.x + u.y * ww.y + u.z * ww.z + u.w * ww.w;
        }
    }
    #pragma unroll
    for (int r = 0; r < 4; r++)
        Hout[(size_t)(b * NN + n0 + r) * F1 + tid] = tanhf(a2[r]);
}

// ---------------- final: max over N, linear head, exp ------------------------
__global__ void __launch_bounds__(160)
final_kernel(const float* __restrict__ Wc, const float* __restrict__ bc,
             float* __restrict__ out)
{
    __shared__ float red[5];
    const int tid = threadIdx.x, b = blockIdx.x;

    const float* base = g_Ha + (size_t)(b * NN) * F1 + tid;   // H6 in g_Ha
    float m = -3.4e38f;
    #pragma unroll 8
    for (int n = 0; n < NN; n++) m = fmaxf(m, base[(size_t)n * F1]);

    float v = m * Wc[tid];
    #pragma unroll
    for (int o = 16; o > 0; o >>= 1) v += __shfl_xor_sync(0xffffffffu, v, o);
    if ((tid & 31) == 0) red[tid >> 5] = v;
    __syncthreads();
    if (tid == 0) {
        float s = 0.f;
        #pragma unroll
        for (int i = 0; i < 5; i++) s += red[i];
        out[b] = expf(s + bc[0]);
    }
}

// ---------------- launch -----------------------------------------------------
extern "C" void kernel_launch(void* const* d_in, const int* in_sizes, int n_in,
                              void* d_out, int out_size)
{
    const float* H    = (const float*)d_in[0];
    const float* w1   = (const float*)d_in[1];
    const float* b1   = (const float*)d_in[2];
    const float* w2   = (const float*)d_in[3];
    const float* b2   = (const float*)d_in[4];
    const float* w3   = (const float*)d_in[5];
    const float* b3   = (const float*)d_in[6];
    const float* w4   = (const float*)d_in[7];
    const float* b4   = (const float*)d_in[8];
    const float* Wdk1 = (const float*)d_in[9];
    const float* bdk1 = (const float*)d_in[10];
    const float* Wdk2 = (const float*)d_in[11];
    const float* bdk2 = (const float*)d_in[12];
    const float* Wt1  = (const float*)d_in[13];
    const float* bt1  = (const float*)d_in[14];
    const float* Wt2  = (const float*)d_in[15];
    const float* bt2  = (const float*)d_in[16];
    const float* Wt3  = (const float*)d_in[17];
    const float* bt3  = (const float*)d_in[18];
    const float* sigw = (const float*)d_in[19];
    const float* Wc   = (const float*)d_in[20];
    const float* bc   = (const float*)d_in[21];
    float* out = (float*)d_out;

    cudaFuncSetAttribute(conv_all, cudaFuncAttributeMaxDynamicSharedMemorySize,
                         SMEM_BYTES);

    conv_all<<<IMG, CT, SMEM_BYTES>>>(H, w1, b1, w2, b2, w3, b3, w4, b4);
    dk_kernel<<<IMG / 8, 256>>>(Wdk1, bdk1, Wdk2, bdk2);
    gram_kernel<<<IMG / 4, 128>>>(sigw);
    round_kernel<<<IMG / 4, 160>>>(0, Wt1, bt1, 1);   // Z=Hf  -> H2 in g_Ha
    round_kernel<<<IMG / 4, 160>>>(1, Wt2, bt2, 2);   // Z=H2  -> H4 in g_Hb
    round_kernel<<<IMG / 4, 160>>>(2, Wt3, bt3, 1);   // Z=H4  -> H6 in g_Ha
    final_kernel<<<NB, 160>>>(Wc, bc, out);
}